// round 3
// baseline (speedup 1.0000x reference)
#include <cuda_runtime.h>
#include <float.h>

#define N_ROWS 32768
#define NUMC   4096
#define DIM    512

#define BM 64
#define BN 128
#define BK 16

// ---- scratch (device globals: no allocation allowed) ----
__device__ float g_z2[NUMC];        // ||z_j||^2 (fp32 tree sum)
__device__ float g_x2[N_ROWS];      // ||x_i||^2
__device__ int   g_bestidx[N_ROWS];
__device__ float g_rowloss[N_ROWS];

typedef unsigned long long ull;

__device__ __forceinline__ ull pack2(float x, float y) {
    ull r;
    asm("mov.b64 %0, {%1, %2};" : "=l"(r) : "f"(x), "f"(y));
    return r;
}
__device__ __forceinline__ void unpack2(ull v, float& lo, float& hi) {
    asm("mov.b64 {%0, %1}, %2;" : "=f"(lo), "=f"(hi) : "l"(v));
}
// Packed dual-fp32 FMA (SASS FFMA2) — PTX-only path, 2x fp32 throughput.
__device__ __forceinline__ ull ffma2(ull a, ull b, ull c) {
    ull d;
    asm("fma.rn.f32x2 %0, %1, %2, %3;" : "=l"(d) : "l"(a), "l"(b), "l"(c));
    return d;
}

// ---- kernel 0: squared row norms (one warp per row) ----
// which==0 -> write g_z2 (nrows=NUMC), which==1 -> write g_x2 (nrows=N_ROWS).
// Destination resolved IN DEVICE CODE (passing __device__ symbols from host is UB).
__global__ void k_sq(const float* __restrict__ src, int which, int nrows) {
    int w = (blockIdx.x * blockDim.x + threadIdx.x) >> 5;
    int lane = threadIdx.x & 31;
    if (w >= nrows) return;
    const float4* row = (const float4*)(src + (size_t)w * DIM);
    float s = 0.f;
#pragma unroll
    for (int i = 0; i < DIM / 4 / 32; i++) {
        float4 v = row[lane + 32 * i];
        s += v.x * v.x + v.y * v.y + v.z * v.z + v.w * v.w;
    }
#pragma unroll
    for (int o = 16; o; o >>= 1) s += __shfl_xor_sync(0xffffffffu, s, o);
    if (lane == 0) {
        if (which) g_x2[w] = s;
        else       g_z2[w] = s;
    }
}

// ---- kernel 1: tiled fp32 GEMM (x @ z^T) with running argmin epilogue ----
// Distance replicates reference rounding exactly:
//   d = fsub_rn( fadd_rn(x2, z2), fmul_rn(2.0f, xz) )
__global__ __launch_bounds__(256) void k_argmin(const float* __restrict__ x,
                                                const float* __restrict__ e) {
    __shared__ ull   As2[BK][BM];        // A values pre-duplicated as (v,v) pairs
    __shared__ float Bs[BK][BN];
    __shared__ float z2s[BN];

    const int tid = threadIdx.x;
    const int tx = tid & 15;             // 0..15 -> 8 cols each
    const int ty = tid >> 4;             // 0..15 -> 4 rows each
    const int rowBase = blockIdx.x * BM;

    const int lr = tid >> 2;             // 0..63
    const int lk = (tid & 3) * 4;        // 0,4,8,12

    float best[4] = {FLT_MAX, FLT_MAX, FLT_MAX, FLT_MAX};
    int   bidx[4] = {0, 0, 0, 0};
    float x2r[4];
#pragma unroll
    for (int m = 0; m < 4; m++) x2r[m] = g_x2[rowBase + ty * 4 + m];

    for (int cb = 0; cb < NUMC; cb += BN) {
        if (tid < BN) z2s[tid] = g_z2[cb + tid];

        ull acc[4][4];
#pragma unroll
        for (int m = 0; m < 4; m++)
#pragma unroll
            for (int p = 0; p < 4; p++) acc[m][p] = 0ull;

        for (int k0 = 0; k0 < DIM; k0 += BK) {
            {
                float4 a = *(const float4*)(x + (size_t)(rowBase + lr) * DIM + k0 + lk);
                As2[lk + 0][lr] = pack2(a.x, a.x);
                As2[lk + 1][lr] = pack2(a.y, a.y);
                As2[lk + 2][lr] = pack2(a.z, a.z);
                As2[lk + 3][lr] = pack2(a.w, a.w);
                float4 b0 = *(const float4*)(e + (size_t)(cb + lr) * DIM + k0 + lk);
                Bs[lk + 0][lr] = b0.x;
                Bs[lk + 1][lr] = b0.y;
                Bs[lk + 2][lr] = b0.z;
                Bs[lk + 3][lr] = b0.w;
                float4 b1 = *(const float4*)(e + (size_t)(cb + lr + 64) * DIM + k0 + lk);
                Bs[lk + 0][lr + 64] = b1.x;
                Bs[lk + 1][lr + 64] = b1.y;
                Bs[lk + 2][lr + 64] = b1.z;
                Bs[lk + 3][lr + 64] = b1.w;
            }
            __syncthreads();
#pragma unroll
            for (int k = 0; k < BK; k++) {
                ulonglong2 a01 = *(const ulonglong2*)&As2[k][ty * 4];
                ulonglong2 a23 = *(const ulonglong2*)&As2[k][ty * 4 + 2];
                ulonglong2 b01 = *(const ulonglong2*)&Bs[k][tx * 8];
                ulonglong2 b23 = *(const ulonglong2*)&Bs[k][tx * 8 + 4];
                ull ad[4] = {a01.x, a01.y, a23.x, a23.y};
                ull bp[4] = {b01.x, b01.y, b23.x, b23.y};
#pragma unroll
                for (int m = 0; m < 4; m++)
#pragma unroll
                    for (int p = 0; p < 4; p++)
                        acc[m][p] = ffma2(ad[m], bp[p], acc[m][p]);
            }
            __syncthreads();
        }

        // epilogue: running argmin of fl(fl(x2+z2) - fl(2*xz)), ascending index order
#pragma unroll
        for (int m = 0; m < 4; m++) {
#pragma unroll
            for (int p = 0; p < 4; p++) {
                float lo, hi;
                unpack2(acc[m][p], lo, hi);
                int n0 = tx * 8 + 2 * p;
                float d0 = __fsub_rn(__fadd_rn(x2r[m], z2s[n0]),     __fmul_rn(2.0f, lo));
                float d1 = __fsub_rn(__fadd_rn(x2r[m], z2s[n0 + 1]), __fmul_rn(2.0f, hi));
                if (d0 < best[m]) { best[m] = d0; bidx[m] = cb + n0; }
                if (d1 < best[m]) { best[m] = d1; bidx[m] = cb + n0 + 1; }
            }
        }
        __syncthreads();   // protect z2s before next chunk overwrites it
    }

    // reduce across the 16 tx-threads of each row (index tie-break = lowest)
#pragma unroll
    for (int m = 0; m < 4; m++) {
        float bd = best[m];
        int bi = bidx[m];
#pragma unroll
        for (int off = 8; off; off >>= 1) {
            float od = __shfl_down_sync(0xffffffffu, bd, off, 16);
            int   oi = __shfl_down_sync(0xffffffffu, bi, off, 16);
            if (od < bd || (od == bd && oi < bi)) { bd = od; bi = oi; }
        }
        if (tx == 0) g_bestidx[rowBase + ty * 4 + m] = bi;
    }
}

// ---- kernel 2: gather nearest code, write vq_out, per-row squared diff ----
__global__ void k_gather(const float* __restrict__ x, const float* __restrict__ e,
                         float* __restrict__ out) {
    int r = (blockIdx.x * blockDim.x + threadIdx.x) >> 5;
    int lane = threadIdx.x & 31;
    if (r >= N_ROWS) return;
    int idx = g_bestidx[r];
    const float4* zr = (const float4*)(e + (size_t)idx * DIM);
    const float4* xr = (const float4*)(x + (size_t)r * DIM);
    float4* orow = (float4*)(out + (size_t)r * DIM);
    float s = 0.f;
#pragma unroll
    for (int i = 0; i < 4; i++) {
        float4 z = zr[lane + 32 * i];
        float4 xv = xr[lane + 32 * i];
        orow[lane + 32 * i] = z;
        float dx = xv.x - z.x, dy = xv.y - z.y, dz = xv.z - z.z, dw = xv.w - z.w;
        s += dx * dx + dy * dy + dz * dz + dw * dw;
    }
#pragma unroll
    for (int o = 16; o; o >>= 1) s += __shfl_xor_sync(0xffffffffu, s, o);
    if (lane == 0) g_rowloss[r] = s;
}

// ---- kernel 3: deterministic loss reduction ----
__global__ void k_loss(float* __restrict__ out, int out_size) {
    __shared__ float sm[1024];
    int t = threadIdx.x;
    float s = 0.f;
    for (int i = t; i < N_ROWS; i += 1024) s += g_rowloss[i];
    sm[t] = s;
    __syncthreads();
    for (int o = 512; o; o >>= 1) {
        if (t < o) sm[t] += sm[t + o];
        __syncthreads();
    }
    if (t == 0) {
        // loss = BETA*mse + GAMMA*mse = 1.25 * mean((x - vq_x)^2)
        out[out_size - 1] = sm[0] * 1.25f / (float)((long long)N_ROWS * DIM);
    }
}

extern "C" void kernel_launch(void* const* d_in, const int* in_sizes, int n_in,
                              void* d_out, int out_size) {
    const float* x = (const float*)d_in[0];
    const float* e = (const float*)d_in[1];
    float* out = (float*)d_out;

    k_sq<<<(NUMC * 32) / 256, 256>>>(e, 0, NUMC);
    k_sq<<<(N_ROWS * 32) / 256, 256>>>(x, 1, N_ROWS);
    k_argmin<<<N_ROWS / BM, 256>>>(x, e);
    k_gather<<<(N_ROWS * 32) / 256, 256>>>(x, e, out);
    k_loss<<<1, 1024>>>(out, out_size);
}

// round 6
// speedup vs baseline: 4.3632x; 4.3632x over previous
#include <cuda_runtime.h>
#include <cuda_bf16.h>
#include <float.h>
#include <cstdint>

#define N_ROWS 32768
#define NUMC   4096
#define DIM    512
#define NCH    128                    // codes per block
#define NCHUNKS ((NUMC / NCH) * 8)    // 32 code blocks x 8 k-chunks = 256

#define ROWPITCH 72                   // bf16 per smem row (144 B) -> conflict-free ldmatrix
#define TILE_S   (128 * ROWPITCH * 2) // 18432 B per operand tile
#define STAGE_S  (4 * TILE_S)         // Ahi, Alo, Bhi, Blo
#define SMEM_TOTAL (512 + 2 * STAGE_S)

#define NCAND 8                       // 4 per n-half warp

// ---- scratch (device globals; no runtime allocation allowed) ----
__device__ __nv_bfloat16 g_xhi[N_ROWS * DIM];
__device__ __nv_bfloat16 g_xlo[N_ROWS * DIM];
__device__ __nv_bfloat16 g_whi[NUMC * DIM];
__device__ __nv_bfloat16 g_wlo[NUMC * DIM];
__device__ float g_z2[NUMC];
__device__ int   g_cand[N_ROWS * NCAND];
__device__ int   g_bestidx[N_ROWS];
__device__ float g_rowloss[N_ROWS];

// ================= helpers =================
__device__ __forceinline__ uint32_t smem_u32(const void* p) {
    uint32_t a;
    asm("{ .reg .u64 t; cvta.to.shared.u64 t, %1; cvt.u32.u64 %0, t; }" : "=r"(a) : "l"(p));
    return a;
}
__device__ __forceinline__ void cp16(uint32_t s, const void* g) {
    asm volatile("cp.async.cg.shared.global [%0], [%1], 16;" :: "r"(s), "l"(g));
}
#define CP_COMMIT() asm volatile("cp.async.commit_group;" ::: "memory")
#define CP_WAIT1()  asm volatile("cp.async.wait_group 1;" ::: "memory")
#define CP_WAIT0()  asm volatile("cp.async.wait_group 0;" ::: "memory")
#define LDSM4(r0, r1, r2, r3, a) \
    asm volatile("ldmatrix.sync.aligned.m8n8.x4.shared.b16 {%0,%1,%2,%3}, [%4];" \
        : "=r"(r0), "=r"(r1), "=r"(r2), "=r"(r3) : "r"(a))

__device__ __forceinline__ void mma16816(float* c, const uint32_t* a,
                                         uint32_t b0, uint32_t b1) {
    asm("mma.sync.aligned.m16n8k16.row.col.f32.bf16.bf16.f32 "
        "{%0,%1,%2,%3}, {%4,%5,%6,%7}, {%8,%9}, {%0,%1,%2,%3};"
        : "+f"(c[0]), "+f"(c[1]), "+f"(c[2]), "+f"(c[3])
        : "r"(a[0]), "r"(a[1]), "r"(a[2]), "r"(a[3]), "r"(b0), "r"(b1));
}

// running top-4 insert (scan is in ascending index order -> strict < keeps lowest idx)
__device__ __forceinline__ void ins4(float t, int idx, float* v, int* ix) {
    if (t < v[3]) {
        if (t < v[1]) {
            v[3] = v[2]; ix[3] = ix[2]; v[2] = v[1]; ix[2] = ix[1];
            if (t < v[0]) { v[1] = v[0]; ix[1] = ix[0]; v[0] = t; ix[0] = idx; }
            else          { v[1] = t; ix[1] = idx; }
        } else {
            if (t < v[2]) { v[3] = v[2]; ix[3] = ix[2]; v[2] = t; ix[2] = idx; }
            else          { v[3] = t; ix[3] = idx; }
        }
    }
}
// tie-aware insert for cross-lane merge
__device__ __forceinline__ void ins4tie(float t, int idx, float* v, int* ix) {
    bool lt3 = (t < v[3]) || (t == v[3] && idx < ix[3]);
    if (lt3) {
        bool lt1 = (t < v[1]) || (t == v[1] && idx < ix[1]);
        if (lt1) {
            v[3] = v[2]; ix[3] = ix[2]; v[2] = v[1]; ix[2] = ix[1];
            bool lt0 = (t < v[0]) || (t == v[0] && idx < ix[0]);
            if (lt0) { v[1] = v[0]; ix[1] = ix[0]; v[0] = t; ix[0] = idx; }
            else     { v[1] = t; ix[1] = idx; }
        } else {
            bool lt2 = (t < v[2]) || (t == v[2] && idx < ix[2]);
            if (lt2) { v[3] = v[2]; ix[3] = ix[2]; v[2] = t; ix[2] = idx; }
            else     { v[3] = t; ix[3] = idx; }
        }
    }
}

// ================= kernel 0: bf16 hi/lo split =================
__global__ void k_split(const float* __restrict__ src, int which, int n) {
    int i = blockIdx.x * blockDim.x + threadIdx.x;
    if (i >= n) return;
    float v = src[i];
    __nv_bfloat16 h = __float2bfloat16(v);
    __nv_bfloat16 l = __float2bfloat16(v - __bfloat162float(h));
    if (which) { g_xhi[i] = h; g_xlo[i] = l; }
    else       { g_whi[i] = h; g_wlo[i] = l; }
}

// ================= kernel 1: exact z2 (one warp per code) =================
__global__ void k_sq(const float* __restrict__ e) {
    int w = (blockIdx.x * blockDim.x + threadIdx.x) >> 5;
    int lane = threadIdx.x & 31;
    if (w >= NUMC) return;
    const float4* row = (const float4*)(e + (size_t)w * DIM);
    float s = 0.f;
#pragma unroll
    for (int i = 0; i < 4; i++) {
        float4 v = row[lane + 32 * i];
        s += v.x * v.x + v.y * v.y + v.z * v.z + v.w * v.w;
    }
#pragma unroll
    for (int o = 16; o; o >>= 1) s += __shfl_xor_sync(0xffffffffu, s, o);
    if (lane == 0) g_z2[w] = s;
}

// ================= kernel 2: HMMA split-GEMM + top-4-per-half candidates =================
__device__ __forceinline__ void prefetch_chunk(uint32_t st, int ci, int rowBase, int tid) {
    int cb = (ci >> 3) * NCH;
    int kc = ci & 7;
#pragma unroll
    for (int j = 0; j < 4; j++) {
        int seg = tid + j * 256;                // 0..1023
        int r = seg >> 3, c16 = seg & 7;
        uint32_t so = (uint32_t)(r * 144 + c16 * 16);
        size_t gA = (size_t)(rowBase + r) * DIM + kc * 64 + c16 * 8;
        size_t gB = (size_t)(cb + r) * DIM + kc * 64 + c16 * 8;
        cp16(st + so,              g_xhi + gA);
        cp16(st + TILE_S + so,     g_xlo + gA);
        cp16(st + 2 * TILE_S + so, g_whi + gB);
        cp16(st + 3 * TILE_S + so, g_wlo + gB);
    }
    CP_COMMIT();
}

__global__ __launch_bounds__(256, 1) void k_mma() {
    extern __shared__ char smem[];
    float* z2s = (float*)smem;                       // 128 floats (512 B)
    const uint32_t sb = smem_u32(smem) + 512;        // stage area, 16B aligned
    const int tid = threadIdx.x;
    const int lane = tid & 31;
    const int wid = tid >> 5;
    const int m0 = (wid >> 1) * 32;                  // warp row origin (CTA-rel)
    const int n0 = (wid & 1) * 64;                   // warp col origin
    const int rowBase = blockIdx.x * 128;

    // ldmatrix lane-relative byte offsets (144 B row pitch)
    const uint32_t a_off = (uint32_t)((lane & 15) * 144 + (lane >> 4) * 16);
    const uint32_t b_off = (uint32_t)((((lane & 7) + ((lane >> 4) << 3)) * 144) +
                                      (((lane >> 3) & 1) * 16));

    float acc[2][8][4];
    float v[4][4];  int ix[4][4];                    // top-4 per row-slot (this n-half)
#pragma unroll
    for (int s = 0; s < 4; s++)
#pragma unroll
        for (int c = 0; c < 4; c++) { v[s][c] = FLT_MAX; ix[s][c] = 0; }

    prefetch_chunk(sb, 0, rowBase, tid);

    for (int ci = 0; ci < NCHUNKS; ci++) {
        const int cb = (ci >> 3) * NCH;
        const int kc = ci & 7;
        if (kc == 0) {
#pragma unroll
            for (int mt = 0; mt < 2; mt++)
#pragma unroll
                for (int nt = 0; nt < 8; nt++)
#pragma unroll
                    for (int c = 0; c < 4; c++) acc[mt][nt][c] = 0.f;
            if (tid < NCH) z2s[tid] = g_z2[cb + tid];
        }

        if (ci + 1 < NCHUNKS) {
            prefetch_chunk(sb + ((ci + 1) & 1) * STAGE_S, ci + 1, rowBase, tid);
            CP_WAIT1();
        } else {
            CP_WAIT0();
        }
        __syncthreads();

        const uint32_t st = sb + (ci & 1) * STAGE_S;
        const uint32_t sAhi = st, sAlo = st + TILE_S;
        const uint32_t sBhi = st + 2 * TILE_S, sBlo = st + 3 * TILE_S;

#pragma unroll
        for (int ks = 0; ks < 4; ks++) {
            const uint32_t kb = (uint32_t)(ks * 32);
            uint32_t ah[2][4], al[2][4];
            LDSM4(ah[0][0], ah[0][1], ah[0][2], ah[0][3], sAhi + (uint32_t)(m0 * 144) + a_off + kb);
            LDSM4(ah[1][0], ah[1][1], ah[1][2], ah[1][3], sAhi + (uint32_t)((m0 + 16) * 144) + a_off + kb);
            LDSM4(al[0][0], al[0][1], al[0][2], al[0][3], sAlo + (uint32_t)(m0 * 144) + a_off + kb);
            LDSM4(al[1][0], al[1][1], al[1][2], al[1][3], sAlo + (uint32_t)((m0 + 16) * 144) + a_off + kb);
#pragma unroll
            for (int p = 0; p < 4; p++) {
                uint32_t bh[4], bl[4];
                LDSM4(bh[0], bh[1], bh[2], bh[3], sBhi + (uint32_t)((n0 + 16 * p) * 144) + b_off + kb);
                LDSM4(bl[0], bl[1], bl[2], bl[3], sBlo + (uint32_t)((n0 + 16 * p) * 144) + b_off + kb);
#pragma unroll
                for (int mt = 0; mt < 2; mt++) {
                    mma16816(acc[mt][2 * p],     ah[mt], bh[0], bh[1]);   // hi*hi
                    mma16816(acc[mt][2 * p + 1], ah[mt], bh[2], bh[3]);
                    mma16816(acc[mt][2 * p],     ah[mt], bl[0], bl[1]);   // hi*lo
                    mma16816(acc[mt][2 * p + 1], ah[mt], bl[2], bl[3]);
                    mma16816(acc[mt][2 * p],     al[mt], bh[0], bh[1]);   // lo*hi
                    mma16816(acc[mt][2 * p + 1], al[mt], bh[2], bh[3]);
                }
            }
        }

        if (kc == 7) {
            // epilogue: rank z2 - 2*xz, running top-4 per row-slot
#pragma unroll
            for (int mt = 0; mt < 2; mt++)
#pragma unroll
                for (int nt = 0; nt < 8; nt++) {
                    int nl = n0 + nt * 8 + (lane & 3) * 2;
                    float z0 = z2s[nl], z1 = z2s[nl + 1];
                    int g0 = cb + nl;
                    ins4(z0 - 2.f * acc[mt][nt][0], g0,     v[mt * 2],     ix[mt * 2]);
                    ins4(z1 - 2.f * acc[mt][nt][1], g0 + 1, v[mt * 2],     ix[mt * 2]);
                    ins4(z0 - 2.f * acc[mt][nt][2], g0,     v[mt * 2 + 1], ix[mt * 2 + 1]);
                    ins4(z1 - 2.f * acc[mt][nt][3], g0 + 1, v[mt * 2 + 1], ix[mt * 2 + 1]);
                }
        }
        __syncthreads();
    }

    // merge top-4 across the 4 lanes (lane%4) sharing each row; tie -> lowest index
#pragma unroll
    for (int s = 0; s < 4; s++) {
#pragma unroll
        for (int step = 1; step <= 2; step <<= 1) {
            float ov[4]; int oi[4];
#pragma unroll
            for (int c = 0; c < 4; c++) {
                ov[c] = __shfl_xor_sync(0xffffffffu, v[s][c], step);
                oi[c] = __shfl_xor_sync(0xffffffffu, ix[s][c], step);
            }
#pragma unroll
            for (int c = 0; c < 4; c++) ins4tie(ov[c], oi[c], v[s], ix[s]);
        }
    }
    // Each warp of the (row-sharing) pair owns a disjoint n-half -> write its own
    // 4 candidate slots: g_cand[row*8 + (wid&1)*4 + c]. NO cross-warp race.
    if ((lane & 3) == 0) {
#pragma unroll
        for (int s = 0; s < 4; s++) {
            int mt = s >> 1, h = s & 1;
            int row = rowBase + m0 + mt * 16 + h * 8 + (lane >> 2);
#pragma unroll
            for (int c = 0; c < 4; c++)
                g_cand[row * NCAND + (wid & 1) * 4 + c] = ix[s][c];
        }
    }
}

// ================= kernel 3: exact fp32 rescore of 8 candidates =================
__global__ void k_rescore(const float* __restrict__ x, const float* __restrict__ e) {
    int gw = (blockIdx.x * blockDim.x + threadIdx.x) >> 5;
    int lane = threadIdx.x & 31;
    if (gw >= N_ROWS) return;
    const float4* xr = (const float4*)(x + (size_t)gw * DIM);
    float4 xv[4];
    float x2p = 0.f;
#pragma unroll
    for (int i = 0; i < 4; i++) {
        xv[i] = xr[lane + 32 * i];
        x2p += xv[i].x * xv[i].x + xv[i].y * xv[i].y + xv[i].z * xv[i].z + xv[i].w * xv[i].w;
    }
#pragma unroll
    for (int o = 16; o; o >>= 1) x2p += __shfl_xor_sync(0xffffffffu, x2p, o);

    float bestd = FLT_MAX;
    int   besti = 0x7fffffff;
#pragma unroll
    for (int c = 0; c < NCAND; c++) {
        int idx = g_cand[gw * NCAND + c];
        const float4* zr = (const float4*)(e + (size_t)idx * DIM);
        float xzp = 0.f, z2p = 0.f;
#pragma unroll
        for (int i = 0; i < 4; i++) {
            float4 z = zr[lane + 32 * i];
            xzp += xv[i].x * z.x + xv[i].y * z.y + xv[i].z * z.z + xv[i].w * z.w;
            z2p += z.x * z.x + z.y * z.y + z.z * z.z + z.w * z.w;
        }
#pragma unroll
        for (int o = 16; o; o >>= 1) {
            xzp += __shfl_xor_sync(0xffffffffu, xzp, o);
            z2p += __shfl_xor_sync(0xffffffffu, z2p, o);
        }
        float d = __fsub_rn(__fadd_rn(x2p, z2p), __fmul_rn(2.0f, xzp));
        if (d < bestd || (d == bestd && idx < besti)) { bestd = d; besti = idx; }
    }
    if (lane == 0) g_bestidx[gw] = besti;
}

// ================= kernel 4: gather + per-row loss =================
__global__ void k_gather(const float* __restrict__ x, const float* __restrict__ e,
                         float* __restrict__ out) {
    int r = (blockIdx.x * blockDim.x + threadIdx.x) >> 5;
    int lane = threadIdx.x & 31;
    if (r >= N_ROWS) return;
    int idx = g_bestidx[r];
    const float4* zr = (const float4*)(e + (size_t)idx * DIM);
    const float4* xr = (const float4*)(x + (size_t)r * DIM);
    float4* orow = (float4*)(out + (size_t)r * DIM);
    float s = 0.f;
#pragma unroll
    for (int i = 0; i < 4; i++) {
        float4 z = zr[lane + 32 * i];
        float4 xv = xr[lane + 32 * i];
        orow[lane + 32 * i] = z;
        float dx = xv.x - z.x, dy = xv.y - z.y, dz = xv.z - z.z, dw = xv.w - z.w;
        s += dx * dx + dy * dy + dz * dz + dw * dw;
    }
#pragma unroll
    for (int o = 16; o; o >>= 1) s += __shfl_xor_sync(0xffffffffu, s, o);
    if (lane == 0) g_rowloss[r] = s;
}

// ================= kernel 5: deterministic loss reduction =================
__global__ void k_loss(float* __restrict__ out, int out_size) {
    __shared__ float sm[1024];
    int t = threadIdx.x;
    float s = 0.f;
    for (int i = t; i < N_ROWS; i += 1024) s += g_rowloss[i];
    sm[t] = s;
    __syncthreads();
    for (int o = 512; o; o >>= 1) {
        if (t < o) sm[t] += sm[t + o];
        __syncthreads();
    }
    if (t == 0) out[out_size - 1] = sm[0] * 1.25f / (float)((long long)N_ROWS * DIM);
}

extern "C" void kernel_launch(void* const* d_in, const int* in_sizes, int n_in,
                              void* d_out, int out_size) {
    const float* x = (const float*)d_in[0];
    const float* e = (const float*)d_in[1];
    float* out = (float*)d_out;

    cudaFuncSetAttribute(k_mma, cudaFuncAttributeMaxDynamicSharedMemorySize, SMEM_TOTAL);

    k_split<<<(N_ROWS * DIM) / 256, 256>>>(x, 1, N_ROWS * DIM);
    k_split<<<(NUMC * DIM) / 256, 256>>>(e, 0, NUMC * DIM);
    k_sq<<<(NUMC * 32) / 256, 256>>>(e);
    k_mma<<<N_ROWS / 128, 256, SMEM_TOTAL>>>();
    k_rescore<<<(N_ROWS * 32) / 256, 256>>>(x, e);
    k_gather<<<(N_ROWS * 32) / 256, 256>>>(x, e, out);
    k_loss<<<1, 1024>>>(out, out_size);
}

// round 7
// speedup vs baseline: 10.2101x; 2.3400x over previous
#include <cuda_runtime.h>
#include <cuda_bf16.h>
#include <float.h>
#include <cstdint>

#define N_ROWS 32768
#define NUMC   4096
#define DIM    512
#define NCH    128                    // codes per block
#define NCHUNKS ((NUMC / NCH) * 8)    // 32 code blocks x 8 k-chunks = 256

#define ROWPITCH 72                   // bf16 per smem row (144 B) -> conflict-free ldmatrix
#define TILE_S   (128 * ROWPITCH * 2) // 18432 B per operand tile
#define STAGE_S  (2 * TILE_S)         // A, B (bf16 only — no lo split)
#define SMEM_TOTAL (512 + 2 * STAGE_S)

#define NCAND 8                       // 4 per n-half warp

// ---- scratch (device globals; no runtime allocation allowed) ----
__device__ __nv_bfloat16 g_xb[N_ROWS * DIM];
__device__ __nv_bfloat16 g_wb[NUMC * DIM];
__device__ float g_z2[NUMC];
__device__ int   g_cand[N_ROWS * NCAND];
__device__ int   g_bestidx[N_ROWS];
__device__ float g_rowloss[N_ROWS];

// ================= helpers =================
__device__ __forceinline__ uint32_t smem_u32(const void* p) {
    uint32_t a;
    asm("{ .reg .u64 t; cvta.to.shared.u64 t, %1; cvt.u32.u64 %0, t; }" : "=r"(a) : "l"(p));
    return a;
}
__device__ __forceinline__ void cp16(uint32_t s, const void* g) {
    asm volatile("cp.async.cg.shared.global [%0], [%1], 16;" :: "r"(s), "l"(g));
}
#define CP_COMMIT() asm volatile("cp.async.commit_group;" ::: "memory")
#define CP_WAIT1()  asm volatile("cp.async.wait_group 1;" ::: "memory")
#define CP_WAIT0()  asm volatile("cp.async.wait_group 0;" ::: "memory")
#define LDSM4(r0, r1, r2, r3, a) \
    asm volatile("ldmatrix.sync.aligned.m8n8.x4.shared.b16 {%0,%1,%2,%3}, [%4];" \
        : "=r"(r0), "=r"(r1), "=r"(r2), "=r"(r3) : "r"(a))

__device__ __forceinline__ void mma16816(float* c, const uint32_t* a,
                                         uint32_t b0, uint32_t b1) {
    asm("mma.sync.aligned.m16n8k16.row.col.f32.bf16.bf16.f32 "
        "{%0,%1,%2,%3}, {%4,%5,%6,%7}, {%8,%9}, {%0,%1,%2,%3};"
        : "+f"(c[0]), "+f"(c[1]), "+f"(c[2]), "+f"(c[3])
        : "r"(a[0]), "r"(a[1]), "r"(a[2]), "r"(a[3]), "r"(b0), "r"(b1));
}

// running top-4 insert (scan is in ascending index order -> strict < keeps lowest idx)
__device__ __forceinline__ void ins4(float t, int idx, float* v, int* ix) {
    if (t < v[3]) {
        if (t < v[1]) {
            v[3] = v[2]; ix[3] = ix[2]; v[2] = v[1]; ix[2] = ix[1];
            if (t < v[0]) { v[1] = v[0]; ix[1] = ix[0]; v[0] = t; ix[0] = idx; }
            else          { v[1] = t; ix[1] = idx; }
        } else {
            if (t < v[2]) { v[3] = v[2]; ix[3] = ix[2]; v[2] = t; ix[2] = idx; }
            else          { v[3] = t; ix[3] = idx; }
        }
    }
}
// tie-aware insert for cross-lane merge
__device__ __forceinline__ void ins4tie(float t, int idx, float* v, int* ix) {
    bool lt3 = (t < v[3]) || (t == v[3] && idx < ix[3]);
    if (lt3) {
        bool lt1 = (t < v[1]) || (t == v[1] && idx < ix[1]);
        if (lt1) {
            v[3] = v[2]; ix[3] = ix[2]; v[2] = v[1]; ix[2] = ix[1];
            bool lt0 = (t < v[0]) || (t == v[0] && idx < ix[0]);
            if (lt0) { v[1] = v[0]; ix[1] = ix[0]; v[0] = t; ix[0] = idx; }
            else     { v[1] = t; ix[1] = idx; }
        } else {
            bool lt2 = (t < v[2]) || (t == v[2] && idx < ix[2]);
            if (lt2) { v[3] = v[2]; ix[3] = ix[2]; v[2] = t; ix[2] = idx; }
            else     { v[3] = t; ix[3] = idx; }
        }
    }
}

// ================= kernel 0: bf16 round =================
__global__ void k_split(const float* __restrict__ src, int which, int n) {
    int i = blockIdx.x * blockDim.x + threadIdx.x;
    if (i >= n) return;
    __nv_bfloat16 h = __float2bfloat16(src[i]);
    if (which) g_xb[i] = h;
    else       g_wb[i] = h;
}

// ================= kernel 1: exact z2 (one warp per code) =================
__global__ void k_sq(const float* __restrict__ e) {
    int w = (blockIdx.x * blockDim.x + threadIdx.x) >> 5;
    int lane = threadIdx.x & 31;
    if (w >= NUMC) return;
    const float4* row = (const float4*)(e + (size_t)w * DIM);
    float s = 0.f;
#pragma unroll
    for (int i = 0; i < 4; i++) {
        float4 v = row[lane + 32 * i];
        s += v.x * v.x + v.y * v.y + v.z * v.z + v.w * v.w;
    }
#pragma unroll
    for (int o = 16; o; o >>= 1) s += __shfl_xor_sync(0xffffffffu, s, o);
    if (lane == 0) g_z2[w] = s;
}

// ================= kernel 2: bf16 HMMA GEMM + top-4-per-half candidates =================
__device__ __forceinline__ void prefetch_chunk(uint32_t st, int ci, int rowBase, int tid) {
    int cb = (ci >> 3) * NCH;
    int kc = ci & 7;
#pragma unroll
    for (int j = 0; j < 4; j++) {
        int seg = tid + j * 256;                // 0..1023
        int r = seg >> 3, c16 = seg & 7;
        uint32_t so = (uint32_t)(r * 144 + c16 * 16);
        size_t gA = (size_t)(rowBase + r) * DIM + kc * 64 + c16 * 8;
        size_t gB = (size_t)(cb + r) * DIM + kc * 64 + c16 * 8;
        cp16(st + so,          g_xb + gA);
        cp16(st + TILE_S + so, g_wb + gB);
    }
    CP_COMMIT();
}

__global__ __launch_bounds__(256, 2) void k_mma() {
    extern __shared__ char smem[];
    float* z2s = (float*)smem;                       // 128 floats (512 B)
    const uint32_t sb = smem_u32(smem) + 512;        // stage area, 16B aligned
    const int tid = threadIdx.x;
    const int lane = tid & 31;
    const int wid = tid >> 5;
    const int m0 = (wid >> 1) * 32;                  // warp row origin (CTA-rel)
    const int n0 = (wid & 1) * 64;                   // warp col origin
    const int rowBase = blockIdx.x * 128;

    // ldmatrix lane-relative byte offsets (144 B row pitch)
    const uint32_t a_off = (uint32_t)((lane & 15) * 144 + (lane >> 4) * 16);
    const uint32_t b_off = (uint32_t)((((lane & 7) + ((lane >> 4) << 3)) * 144) +
                                      (((lane >> 3) & 1) * 16));

    float acc[2][8][4];
    float v[4][4];  int ix[4][4];                    // top-4 per row-slot (this n-half)
#pragma unroll
    for (int s = 0; s < 4; s++)
#pragma unroll
        for (int c = 0; c < 4; c++) { v[s][c] = FLT_MAX; ix[s][c] = 0; }

    prefetch_chunk(sb, 0, rowBase, tid);

    for (int ci = 0; ci < NCHUNKS; ci++) {
        const int cb = (ci >> 3) * NCH;
        const int kc = ci & 7;
        if (kc == 0) {
#pragma unroll
            for (int mt = 0; mt < 2; mt++)
#pragma unroll
                for (int nt = 0; nt < 8; nt++)
#pragma unroll
                    for (int c = 0; c < 4; c++) acc[mt][nt][c] = 0.f;
            if (tid < NCH) z2s[tid] = g_z2[cb + tid];
        }

        if (ci + 1 < NCHUNKS) {
            prefetch_chunk(sb + ((ci + 1) & 1) * STAGE_S, ci + 1, rowBase, tid);
            CP_WAIT1();
        } else {
            CP_WAIT0();
        }
        __syncthreads();

        const uint32_t st = sb + (ci & 1) * STAGE_S;
        const uint32_t sA = st, sB = st + TILE_S;

#pragma unroll
        for (int ks = 0; ks < 4; ks++) {
            const uint32_t kb = (uint32_t)(ks * 32);
            uint32_t ah[2][4];
            LDSM4(ah[0][0], ah[0][1], ah[0][2], ah[0][3], sA + (uint32_t)(m0 * 144) + a_off + kb);
            LDSM4(ah[1][0], ah[1][1], ah[1][2], ah[1][3], sA + (uint32_t)((m0 + 16) * 144) + a_off + kb);
#pragma unroll
            for (int p = 0; p < 4; p++) {
                uint32_t bh[4];
                LDSM4(bh[0], bh[1], bh[2], bh[3], sB + (uint32_t)((n0 + 16 * p) * 144) + b_off + kb);
#pragma unroll
                for (int mt = 0; mt < 2; mt++) {
                    mma16816(acc[mt][2 * p],     ah[mt], bh[0], bh[1]);
                    mma16816(acc[mt][2 * p + 1], ah[mt], bh[2], bh[3]);
                }
            }
        }

        if (kc == 7) {
            // epilogue: rank z2 - 2*xz, running top-4 per row-slot
#pragma unroll
            for (int mt = 0; mt < 2; mt++)
#pragma unroll
                for (int nt = 0; nt < 8; nt++) {
                    int nl = n0 + nt * 8 + (lane & 3) * 2;
                    float z0 = z2s[nl], z1 = z2s[nl + 1];
                    int g0 = cb + nl;
                    ins4(z0 - 2.f * acc[mt][nt][0], g0,     v[mt * 2],     ix[mt * 2]);
                    ins4(z1 - 2.f * acc[mt][nt][1], g0 + 1, v[mt * 2],     ix[mt * 2]);
                    ins4(z0 - 2.f * acc[mt][nt][2], g0,     v[mt * 2 + 1], ix[mt * 2 + 1]);
                    ins4(z1 - 2.f * acc[mt][nt][3], g0 + 1, v[mt * 2 + 1], ix[mt * 2 + 1]);
                }
        }
        __syncthreads();
    }

    // merge top-4 across the 4 lanes (lane%4) sharing each row; tie -> lowest index
#pragma unroll
    for (int s = 0; s < 4; s++) {
#pragma unroll
        for (int step = 1; step <= 2; step <<= 1) {
            float ov[4]; int oi[4];
#pragma unroll
            for (int c = 0; c < 4; c++) {
                ov[c] = __shfl_xor_sync(0xffffffffu, v[s][c], step);
                oi[c] = __shfl_xor_sync(0xffffffffu, ix[s][c], step);
            }
#pragma unroll
            for (int c = 0; c < 4; c++) ins4tie(ov[c], oi[c], v[s], ix[s]);
        }
    }
    // each warp of the row-sharing pair owns a disjoint n-half -> disjoint slots
    if ((lane & 3) == 0) {
#pragma unroll
        for (int s = 0; s < 4; s++) {
            int mt = s >> 1, h = s & 1;
            int row = rowBase + m0 + mt * 16 + h * 8 + (lane >> 2);
#pragma unroll
            for (int c = 0; c < 4; c++)
                g_cand[row * NCAND + (wid & 1) * 4 + c] = ix[s][c];
        }
    }
}

// ================= kernel 3: exact fp32 rescore of 8 candidates =================
__global__ void k_rescore(const float* __restrict__ x, const float* __restrict__ e) {
    int gw = (blockIdx.x * blockDim.x + threadIdx.x) >> 5;
    int lane = threadIdx.x & 31;
    if (gw >= N_ROWS) return;
    const float4* xr = (const float4*)(x + (size_t)gw * DIM);
    float4 xv[4];
    float x2p = 0.f;
#pragma unroll
    for (int i = 0; i < 4; i++) {
        xv[i] = xr[lane + 32 * i];
        x2p += xv[i].x * xv[i].x + xv[i].y * xv[i].y + xv[i].z * xv[i].z + xv[i].w * xv[i].w;
    }
#pragma unroll
    for (int o = 16; o; o >>= 1) x2p += __shfl_xor_sync(0xffffffffu, x2p, o);

    float bestd = FLT_MAX;
    int   besti = 0x7fffffff;
#pragma unroll
    for (int c = 0; c < NCAND; c++) {
        int idx = g_cand[gw * NCAND + c];
        const float4* zr = (const float4*)(e + (size_t)idx * DIM);
        float xzp = 0.f, z2p = 0.f;
#pragma unroll
        for (int i = 0; i < 4; i++) {
            float4 z = zr[lane + 32 * i];
            xzp += xv[i].x * z.x + xv[i].y * z.y + xv[i].z * z.z + xv[i].w * z.w;
            z2p += z.x * z.x + z.y * z.y + z.z * z.z + z.w * z.w;
        }
#pragma unroll
        for (int o = 16; o; o >>= 1) {
            xzp += __shfl_xor_sync(0xffffffffu, xzp, o);
            z2p += __shfl_xor_sync(0xffffffffu, z2p, o);
        }
        float d = __fsub_rn(__fadd_rn(x2p, z2p), __fmul_rn(2.0f, xzp));
        if (d < bestd || (d == bestd && idx < besti)) { bestd = d; besti = idx; }
    }
    if (lane == 0) g_bestidx[gw] = besti;
}

// ================= kernel 4: gather + per-row loss =================
__global__ void k_gather(const float* __restrict__ x, const float* __restrict__ e,
                         float* __restrict__ out) {
    int r = (blockIdx.x * blockDim.x + threadIdx.x) >> 5;
    int lane = threadIdx.x & 31;
    if (r >= N_ROWS) return;
    int idx = g_bestidx[r];
    const float4* zr = (const float4*)(e + (size_t)idx * DIM);
    const float4* xr = (const float4*)(x + (size_t)r * DIM);
    float4* orow = (float4*)(out + (size_t)r * DIM);
    float s = 0.f;
#pragma unroll
    for (int i = 0; i < 4; i++) {
        float4 z = zr[lane + 32 * i];
        float4 xv = xr[lane + 32 * i];
        orow[lane + 32 * i] = z;
        float dx = xv.x - z.x, dy = xv.y - z.y, dz = xv.z - z.z, dw = xv.w - z.w;
        s += dx * dx + dy * dy + dz * dz + dw * dw;
    }
#pragma unroll
    for (int o = 16; o; o >>= 1) s += __shfl_xor_sync(0xffffffffu, s, o);
    if (lane == 0) g_rowloss[r] = s;
}

// ================= kernel 5: deterministic loss reduction =================
__global__ void k_loss(float* __restrict__ out, int out_size) {
    __shared__ float sm[1024];
    int t = threadIdx.x;
    float s = 0.f;
    for (int i = t; i < N_ROWS; i += 1024) s += g_rowloss[i];
    sm[t] = s;
    __syncthreads();
    for (int o = 512; o; o >>= 1) {
        if (t < o) sm[t] += sm[t + o];
        __syncthreads();
    }
    if (t == 0) out[out_size - 1] = sm[0] * 1.25f / (float)((long long)N_ROWS * DIM);
}

extern "C" void kernel_launch(void* const* d_in, const int* in_sizes, int n_in,
                              void* d_out, int out_size) {
    const float* x = (const float*)d_in[0];
    const float* e = (const float*)d_in[1];
    float* out = (float*)d_out;

    cudaFuncSetAttribute(k_mma, cudaFuncAttributeMaxDynamicSharedMemorySize, SMEM_TOTAL);

    k_split<<<(N_ROWS * DIM) / 256, 256>>>(x, 1, N_ROWS * DIM);
    k_split<<<(NUMC * DIM) / 256, 256>>>(e, 0, NUMC * DIM);
    k_sq<<<(NUMC * 32) / 256, 256>>>(e);
    k_mma<<<N_ROWS / 128, 256, SMEM_TOTAL>>>();
    k_rescore<<<(N_ROWS * 32) / 256, 256>>>(x, e);
    k_gather<<<(N_ROWS * 32) / 256, 256>>>(x, e, out);
    k_loss<<<1, 1024>>>(out, out_size);
}